// round 4
// baseline (speedup 1.0000x reference)
#include <cuda_runtime.h>
#include <cuda_bf16.h>
#include <cstdint>

// out[i] = 0.1 * x[i] * sum_j A[i][j] * (1 - x[j])
// HBM-bound fp32 matvec. A (1 GiB) streamed once with 256-bit evict-first
// loads (LDG.E.256, sm_100+), x served from L1. Warp-per-row, MLP=4 -> 4 KB
// of A in flight per warp iteration.

#define WARPS_PER_BLOCK 8
#define THREADS (WARPS_PER_BLOCK * 32)

struct F8 { float v[8]; };

__device__ __forceinline__ F8 ldg256_cs(const float* p) {
    F8 r;
    asm("ld.global.cs.v8.f32 {%0,%1,%2,%3,%4,%5,%6,%7}, [%8];"
        : "=f"(r.v[0]), "=f"(r.v[1]), "=f"(r.v[2]), "=f"(r.v[3]),
          "=f"(r.v[4]), "=f"(r.v[5]), "=f"(r.v[6]), "=f"(r.v[7])
        : "l"(p));
    return r;
}

__global__ void __launch_bounds__(THREADS)
epidemic_matvec_kernel(const float* __restrict__ x,
                       const float* __restrict__ A,
                       float* __restrict__ out,
                       int n)
{
    const int tid  = threadIdx.x;
    const int warp = tid >> 5;
    const int lane = tid & 31;
    const int row  = blockIdx.x * WARPS_PER_BLOCK + warp;
    if (row >= n) return;

    const int nv8 = n >> 3;   // float8 chunks per row
    const float* __restrict__ Arow = A + (size_t)row * (size_t)n;
    const float4* __restrict__ x4  = reinterpret_cast<const float4*>(x);

    float s0 = 0.0f, s1 = 0.0f, s2 = 0.0f, s3 = 0.0f;

    int k = lane;
    // Front-batch 4 independent 256-bit streaming loads on A (4 KB / warp /
    // iteration), then consume with L1-hit x loads.
    for (; k + 96 < nv8; k += 128) {
        F8 a0 = ldg256_cs(Arow + ((size_t)(k)      << 3));
        F8 a1 = ldg256_cs(Arow + ((size_t)(k + 32) << 3));
        F8 a2 = ldg256_cs(Arow + ((size_t)(k + 64) << 3));
        F8 a3 = ldg256_cs(Arow + ((size_t)(k + 96) << 3));

        {
            float4 b0 = x4[2 * k],     b1 = x4[2 * k + 1];
            s0 += a0.v[0]*(1.0f-b0.x) + a0.v[1]*(1.0f-b0.y)
                + a0.v[2]*(1.0f-b0.z) + a0.v[3]*(1.0f-b0.w)
                + a0.v[4]*(1.0f-b1.x) + a0.v[5]*(1.0f-b1.y)
                + a0.v[6]*(1.0f-b1.z) + a0.v[7]*(1.0f-b1.w);
        }
        {
            float4 b0 = x4[2 * (k+32)], b1 = x4[2 * (k+32) + 1];
            s1 += a1.v[0]*(1.0f-b0.x) + a1.v[1]*(1.0f-b0.y)
                + a1.v[2]*(1.0f-b0.z) + a1.v[3]*(1.0f-b0.w)
                + a1.v[4]*(1.0f-b1.x) + a1.v[5]*(1.0f-b1.y)
                + a1.v[6]*(1.0f-b1.z) + a1.v[7]*(1.0f-b1.w);
        }
        {
            float4 b0 = x4[2 * (k+64)], b1 = x4[2 * (k+64) + 1];
            s2 += a2.v[0]*(1.0f-b0.x) + a2.v[1]*(1.0f-b0.y)
                + a2.v[2]*(1.0f-b0.z) + a2.v[3]*(1.0f-b0.w)
                + a2.v[4]*(1.0f-b1.x) + a2.v[5]*(1.0f-b1.y)
                + a2.v[6]*(1.0f-b1.z) + a2.v[7]*(1.0f-b1.w);
        }
        {
            float4 b0 = x4[2 * (k+96)], b1 = x4[2 * (k+96) + 1];
            s3 += a3.v[0]*(1.0f-b0.x) + a3.v[1]*(1.0f-b0.y)
                + a3.v[2]*(1.0f-b0.z) + a3.v[3]*(1.0f-b0.w)
                + a3.v[4]*(1.0f-b1.x) + a3.v[5]*(1.0f-b1.y)
                + a3.v[6]*(1.0f-b1.z) + a3.v[7]*(1.0f-b1.w);
        }
    }
    // float8 tail
    for (; k < nv8; k += 32) {
        F8 a0 = ldg256_cs(Arow + ((size_t)k << 3));
        float4 b0 = x4[2 * k], b1 = x4[2 * k + 1];
        s0 += a0.v[0]*(1.0f-b0.x) + a0.v[1]*(1.0f-b0.y)
            + a0.v[2]*(1.0f-b0.z) + a0.v[3]*(1.0f-b0.w)
            + a0.v[4]*(1.0f-b1.x) + a0.v[5]*(1.0f-b1.y)
            + a0.v[6]*(1.0f-b1.z) + a0.v[7]*(1.0f-b1.w);
    }
    // scalar tail (n not a multiple of 8)
    for (int j = (nv8 << 3) + lane; j < n; j += 32) {
        s0 += Arow[j] * (1.0f - x[j]);
    }

    float sum = (s0 + s1) + (s2 + s3);
    #pragma unroll
    for (int off = 16; off > 0; off >>= 1)
        sum += __shfl_xor_sync(0xFFFFFFFFu, sum, off);

    if (lane == 0) {
        out[row] = 0.1f * x[row] * sum;
    }
}

extern "C" void kernel_launch(void* const* d_in, const int* in_sizes, int n_in,
                              void* d_out, int out_size)
{
    // metadata order: t (unused), x [n], A [n*n]
    const float* x = (const float*)d_in[1];
    const float* A = (const float*)d_in[2];
    float* out     = (float*)d_out;
    const int n    = in_sizes[1];

    const int blocks = (n + WARPS_PER_BLOCK - 1) / WARPS_PER_BLOCK;
    epidemic_matvec_kernel<<<blocks, THREADS>>>(x, A, out, n);
}

// round 6
// speedup vs baseline: 1.0670x; 1.0670x over previous
#include <cuda_runtime.h>
#include <cuda_bf16.h>
#include <cstdint>

// out[i] = 0.1 * x[i] * sum_j A[i][j] * (1 - x[j])
// HBM-bound fp32 matvec. A (1 GiB) streamed once with evict-first LDG.128.
// K-split: each warp handles one (row, segment) pair (segment = n/8 cols)
// -> 16384 blocks -> ~28 waves -> negligible wave-quantization tail.
// Partials combined via atomicAdd; out zeroed by a tiny init kernel.

#define WARPS_PER_BLOCK 8
#define THREADS (WARPS_PER_BLOCK * 32)
#define SEG 8

__global__ void init_out_kernel(float* __restrict__ out, int n)
{
    int i = blockIdx.x * blockDim.x + threadIdx.x;
    if (i < n) out[i] = 0.0f;
}

__global__ void __launch_bounds__(THREADS)
epidemic_matvec_kernel(const float* __restrict__ x,
                       const float* __restrict__ A,
                       float* __restrict__ out,
                       int n, int seg_len)
{
    const int tid    = threadIdx.x;
    const int lane   = tid & 31;
    const int warpId = blockIdx.x * WARPS_PER_BLOCK + (tid >> 5);
    if (warpId >= n * SEG) return;

    const int row = warpId >> 3;        // warpId / SEG
    const int seg = warpId & (SEG - 1); // warpId % SEG
    const int j0  = seg * seg_len;
    const int j1  = min(n, j0 + seg_len);
    if (j0 >= n) return;

    const float* __restrict__ Arow = A + (size_t)row * (size_t)n;

    float s0 = 0.0f, s1 = 0.0f, s2 = 0.0f, s3 = 0.0f;

    if (((n & 3) == 0)) {
        // vector path: seg_len is a multiple of 8, so Arow+j0 and x+j0 are
        // 32B-aligned when the row base is 16B-aligned (n multiple of 4).
        const float4* __restrict__ A4 = reinterpret_cast<const float4*>(Arow + j0);
        const float4* __restrict__ x4 = reinterpret_cast<const float4*>(x + j0);
        const int nv = (j1 - j0) >> 2;

        int k = lane;
        // Front-batch 4 independent streaming LDG.128 on A (MLP=4).
        for (; k + 96 < nv; k += 128) {
            float4 a0 = __ldcs(&A4[k]);
            float4 a1 = __ldcs(&A4[k + 32]);
            float4 a2 = __ldcs(&A4[k + 64]);
            float4 a3 = __ldcs(&A4[k + 96]);
            float4 b0 = x4[k];
            float4 b1 = x4[k + 32];
            float4 b2 = x4[k + 64];
            float4 b3 = x4[k + 96];
            s0 += a0.x * (1.0f - b0.x) + a0.y * (1.0f - b0.y)
                + a0.z * (1.0f - b0.z) + a0.w * (1.0f - b0.w);
            s1 += a1.x * (1.0f - b1.x) + a1.y * (1.0f - b1.y)
                + a1.z * (1.0f - b1.z) + a1.w * (1.0f - b1.w);
            s2 += a2.x * (1.0f - b2.x) + a2.y * (1.0f - b2.y)
                + a2.z * (1.0f - b2.z) + a2.w * (1.0f - b2.w);
            s3 += a3.x * (1.0f - b3.x) + a3.y * (1.0f - b3.y)
                + a3.z * (1.0f - b3.z) + a3.w * (1.0f - b3.w);
        }
        for (; k < nv; k += 32) {
            float4 a0 = __ldcs(&A4[k]);
            float4 b0 = x4[k];
            s0 += a0.x * (1.0f - b0.x) + a0.y * (1.0f - b0.y)
                + a0.z * (1.0f - b0.z) + a0.w * (1.0f - b0.w);
        }
        // scalar remainder within segment
        for (int j = j0 + (nv << 2) + lane; j < j1; j += 32)
            s0 += Arow[j] * (1.0f - x[j]);
    } else {
        // general scalar fallback
        for (int j = j0 + lane; j < j1; j += 32)
            s0 += Arow[j] * (1.0f - x[j]);
    }

    float sum = (s0 + s1) + (s2 + s3);
    #pragma unroll
    for (int off = 16; off > 0; off >>= 1)
        sum += __shfl_xor_sync(0xFFFFFFFFu, sum, off);

    if (lane == 0) {
        atomicAdd(&out[row], 0.1f * x[row] * sum);
    }
}

extern "C" void kernel_launch(void* const* d_in, const int* in_sizes, int n_in,
                              void* d_out, int out_size)
{
    // metadata order: t (unused), x [n], A [n*n]
    const float* x = (const float*)d_in[1];
    const float* A = (const float*)d_in[2];
    float* out     = (float*)d_out;
    const int n    = in_sizes[1];

    init_out_kernel<<<(n + 255) / 256, 256>>>(out, n);

    // seg_len: multiple of 8 so segment bases stay 32B-aligned
    int seg_len = (n + SEG - 1) / SEG;
    seg_len = (seg_len + 7) & ~7;

    const long long total_warps = (long long)n * SEG;
    const int blocks = (int)((total_warps + WARPS_PER_BLOCK - 1) / WARPS_PER_BLOCK);
    epidemic_matvec_kernel<<<blocks, THREADS>>>(x, A, out, n, seg_len);
}